// round 6
// baseline (speedup 1.0000x reference)
#include <cuda_runtime.h>
#include <cstdint>

// Problem constants (match reference setup_inputs)
#define FEAT        128
#define NUM_GRAPHS  10000

// Tuning
#define ROWS_PER_WARP   128   // avg segment length ~100 rows -> ~2.3 segs/chunk
#define WARPS_PER_BLOCK 8
#define BLOCK_THREADS   (WARPS_PER_BLOCK * 32)

// Device-global flag: element stride of the batch buffer in int32 words
// (1 = int32 indices, 2 = int64 indices, low word read).
__device__ int g_idx_stride;

// ---------------------------------------------------------------------------
// Kernel 1 (prologue): zero the output AND detect the batch dtype.
// Detection (block 0, warp 0): read 32 odd-indexed int32 words near the end
// of the n-word-safe region. Little-endian int64 with values < 2^31 -> odd
// words are zero high-halves. int32 sorted data -> tail values ~9999 != 0.
// ---------------------------------------------------------------------------
__global__ void prologue_kernel(float4* __restrict__ out, int n4,
                                const int* __restrict__ braw, int n) {
    if (blockIdx.x == 0 && threadIdx.x < 32) {
        int lane = threadIdx.x;
        int idx = n - 1 - 2 * lane;
        if (!(idx & 1)) idx -= 1;            // force odd index
        int nonzero = (idx > 0) ? (braw[idx] != 0) : 0;
        nonzero = __any_sync(0xFFFFFFFF, nonzero);
        if (lane == 0) g_idx_stride = nonzero ? 1 : 2;
    }
    int i = blockIdx.x * blockDim.x + threadIdx.x;
    if (i < n4) out[i] = make_float4(0.f, 0.f, 0.f, 0.f);
}

// ---------------------------------------------------------------------------
// Kernel 2: sorted segment sum.
// One warp owns ROWS_PER_WARP contiguous rows; each lane owns 4 features.
// Sortedness shortcut: per 8-row group, load ONLY the last id s7. Since the
// ids are nondecreasing, s7 == cur implies all 8 ids == cur -> fast path is
// pure accumulation (no branches, no extra index loads). Otherwise take the
// rare slow path with per-row logic. Flushes go through atomicAdd because
// chunk boundaries can split a segment across warps.
// ---------------------------------------------------------------------------
__device__ __forceinline__ void flush_acc(float* __restrict__ out,
                                          int seg, int lane, const float4& acc,
                                          int max_seg) {
    if (seg < 0 || seg >= max_seg) return;  // insurance against bad ids
    float* p = out + (size_t)seg * FEAT + lane * 4;
    atomicAdd(p + 0, acc.x);
    atomicAdd(p + 1, acc.y);
    atomicAdd(p + 2, acc.z);
    atomicAdd(p + 3, acc.w);
}

__global__ __launch_bounds__(BLOCK_THREADS, 5)
void seg_sum_kernel(const float4* __restrict__ h,     // [n_rows][32] float4
                    const int* __restrict__ braw,     // batch, stride words
                    float* __restrict__ out,          // [max_seg][FEAT]
                    int n_rows, int max_seg) {
    const int warp_id = blockIdx.x * WARPS_PER_BLOCK + (threadIdx.x >> 5);
    const int lane    = threadIdx.x & 31;
    const int stride  = g_idx_stride;  // 1 (int32) or 2 (int64 low word)

    int start = warp_id * ROWS_PER_WARP;
    if (start >= n_rows) return;
    int end = min(start + ROWS_PER_WARP, n_rows);

    float4 acc = make_float4(0.f, 0.f, 0.f, 0.f);
    int cur = braw[start * stride];

    int r = start;
    for (; r + 8 <= end; r += 8) {
        // One warp-uniform index load per 8 rows (sorted => s7==cur covers all)
        int s7 = braw[(r + 7) * stride];

        float4 v[8];
        #pragma unroll
        for (int j = 0; j < 8; ++j)
            v[j] = __ldcs(&h[(size_t)(r + j) * 32 + lane]);

        if (s7 == cur) {
            // Fast path: tree-sum the 8 rows, single dependency on acc.
            float4 t01, t23, t45, t67, t03, t47, t;
            t01.x = v[0].x + v[1].x; t01.y = v[0].y + v[1].y; t01.z = v[0].z + v[1].z; t01.w = v[0].w + v[1].w;
            t23.x = v[2].x + v[3].x; t23.y = v[2].y + v[3].y; t23.z = v[2].z + v[3].z; t23.w = v[2].w + v[3].w;
            t45.x = v[4].x + v[5].x; t45.y = v[4].y + v[5].y; t45.z = v[4].z + v[5].z; t45.w = v[4].w + v[5].w;
            t67.x = v[6].x + v[7].x; t67.y = v[6].y + v[7].y; t67.z = v[6].z + v[7].z; t67.w = v[6].w + v[7].w;
            t03.x = t01.x + t23.x; t03.y = t01.y + t23.y; t03.z = t01.z + t23.z; t03.w = t01.w + t23.w;
            t47.x = t45.x + t67.x; t47.y = t45.y + t67.y; t47.z = t45.z + t67.z; t47.w = t45.w + t67.w;
            t.x = t03.x + t47.x; t.y = t03.y + t47.y; t.z = t03.z + t47.z; t.w = t03.w + t47.w;
            acc.x += t.x; acc.y += t.y; acc.z += t.z; acc.w += t.w;
        } else {
            // Slow path (segment boundary inside this group): per-row logic.
            #pragma unroll
            for (int j = 0; j < 8; ++j) {
                int s = braw[(r + j) * stride];
                if (s != cur) {
                    flush_acc(out, cur, lane, acc, max_seg);
                    cur = s;
                    acc = make_float4(0.f, 0.f, 0.f, 0.f);
                }
                acc.x += v[j].x; acc.y += v[j].y; acc.z += v[j].z; acc.w += v[j].w;
            }
        }
    }
    // Tail
    for (; r < end; ++r) {
        int s = braw[r * stride];
        float4 vv = __ldcs(&h[(size_t)r * 32 + lane]);
        if (s != cur) {
            flush_acc(out, cur, lane, acc, max_seg);
            cur = s;
            acc = make_float4(0.f, 0.f, 0.f, 0.f);
        }
        acc.x += vv.x; acc.y += vv.y; acc.z += vv.z; acc.w += vv.w;
    }
    // Final flush
    flush_acc(out, cur, lane, acc, max_seg);
}

// ---------------------------------------------------------------------------
// Launch. Inputs: h_t (float32, N*FEAT) and batch (int32 or int64, N).
// Order disambiguated by element count (h_t is FEAT x larger).
// ---------------------------------------------------------------------------
extern "C" void kernel_launch(void* const* d_in, const int* in_sizes, int n_in,
                              void* d_out, int out_size) {
    int hi = 0, bi = 1;
    if (n_in >= 2 && in_sizes[0] < in_sizes[1]) { hi = 1; bi = 0; }

    const float4* h        = (const float4*)d_in[hi];
    const int*    batchRaw = (const int*)d_in[bi];
    float*        out      = (float*)d_out;

    const int n_rows  = in_sizes[bi];
    const int max_seg = out_size / FEAT;

    // 1) fused zero + dtype detect
    int n4 = out_size / 4;
    prologue_kernel<<<(n4 + 255) / 256, 256>>>((float4*)d_out, n4,
                                               batchRaw, n_rows);

    // 2) segment sum
    int n_warps  = (n_rows + ROWS_PER_WARP - 1) / ROWS_PER_WARP;
    int n_blocks = (n_warps + WARPS_PER_BLOCK - 1) / WARPS_PER_BLOCK;
    seg_sum_kernel<<<n_blocks, BLOCK_THREADS>>>(h, batchRaw, out, n_rows, max_seg);
}

// round 7
// speedup vs baseline: 1.0004x; 1.0004x over previous
#include <cuda_runtime.h>
#include <cstdint>

// Problem constants (match reference setup_inputs)
#define FEAT        128

// Launch shape: exactly one balanced wave on GB300 (152 SMs; use 148 to be
// safe across parts) x 5 CTAs/SM resident (regs<=48 at 256 thr).
#define NUM_SMS         148
#define CTAS_PER_SM     5
#define WARPS_PER_BLOCK 8
#define BLOCK_THREADS   (WARPS_PER_BLOCK * 32)
#define TOTAL_CTAS      (NUM_SMS * CTAS_PER_SM)
#define TOTAL_WARPS     (TOTAL_CTAS * WARPS_PER_BLOCK)   // 5920

// Device-global flag: element stride of the batch buffer in int32 words
// (1 = int32 indices, 2 = int64 indices, low word read).
__device__ int g_idx_stride;

// ---------------------------------------------------------------------------
// Kernel 1 (prologue): zero the output AND detect the batch dtype.
// Detection (block 0, warp 0): read 32 odd-indexed int32 words near the end
// of the n-word-safe region. Little-endian int64 with values < 2^31 -> odd
// words are zero high-halves. int32 sorted data -> tail values ~9999 != 0.
// ---------------------------------------------------------------------------
__global__ void prologue_kernel(float4* __restrict__ out, int n4,
                                const int* __restrict__ braw, int n) {
    if (blockIdx.x == 0 && threadIdx.x < 32) {
        int lane = threadIdx.x;
        int idx = n - 1 - 2 * lane;
        if (!(idx & 1)) idx -= 1;            // force odd index
        int nonzero = (idx > 0) ? (braw[idx] != 0) : 0;
        nonzero = __any_sync(0xFFFFFFFF, nonzero);
        if (lane == 0) g_idx_stride = nonzero ? 1 : 2;
    }
    int i = blockIdx.x * blockDim.x + threadIdx.x;
    if (i < n4) out[i] = make_float4(0.f, 0.f, 0.f, 0.f);
}

// ---------------------------------------------------------------------------
// Kernel 2: sorted segment sum, single balanced wave.
// The row range [0, n_rows) is split evenly across TOTAL_WARPS warps
// (difference of at most one row), so every warp finishes at the same time.
// Each lane owns 4 features (one LDG.128 per row). Sortedness shortcut:
// per 8-row group load only the LAST id; equality with cur implies the whole
// group is one segment -> branch-free tree accumulation. atomicAdd flush on
// segment change / range end (ranges can split a segment across warps).
// ---------------------------------------------------------------------------
__device__ __forceinline__ void flush_acc(float* __restrict__ out,
                                          int seg, int lane, const float4& acc,
                                          int max_seg) {
    if (seg < 0 || seg >= max_seg) return;  // insurance against bad ids
    float* p = out + (size_t)seg * FEAT + lane * 4;
    atomicAdd(p + 0, acc.x);
    atomicAdd(p + 1, acc.y);
    atomicAdd(p + 2, acc.z);
    atomicAdd(p + 3, acc.w);
}

__global__ __launch_bounds__(BLOCK_THREADS, CTAS_PER_SM)
void seg_sum_kernel(const float4* __restrict__ h,     // [n_rows][32] float4
                    const int* __restrict__ braw,     // batch, stride words
                    float* __restrict__ out,          // [max_seg][FEAT]
                    int n_rows, int max_seg) {
    const int warp_id = blockIdx.x * WARPS_PER_BLOCK + (threadIdx.x >> 5);
    const int lane    = threadIdx.x & 31;
    const int stride  = g_idx_stride;  // 1 (int32) or 2 (int64 low word)

    // Even split: first `rem` warps get q+1 rows, the rest get q.
    const int q   = n_rows / TOTAL_WARPS;
    const int rem = n_rows - q * TOTAL_WARPS;
    int start, cnt;
    if (warp_id < rem) { cnt = q + 1; start = warp_id * (q + 1); }
    else               { cnt = q;     start = warp_id * q + rem; }
    if (cnt <= 0) return;
    int end = start + cnt;

    float4 acc = make_float4(0.f, 0.f, 0.f, 0.f);
    int cur = braw[start * stride];

    int r = start;
    for (; r + 8 <= end; r += 8) {
        // One warp-uniform index load per 8 rows (sorted => s7==cur covers all)
        int s7 = braw[(r + 7) * stride];

        float4 v[8];
        #pragma unroll
        for (int j = 0; j < 8; ++j)
            v[j] = __ldcs(&h[(size_t)(r + j) * 32 + lane]);

        if (s7 == cur) {
            // Fast path: tree-sum the 8 rows, single dependency on acc.
            float4 t01, t23, t45, t67, t03, t47, t;
            t01.x = v[0].x + v[1].x; t01.y = v[0].y + v[1].y; t01.z = v[0].z + v[1].z; t01.w = v[0].w + v[1].w;
            t23.x = v[2].x + v[3].x; t23.y = v[2].y + v[3].y; t23.z = v[2].z + v[3].z; t23.w = v[2].w + v[3].w;
            t45.x = v[4].x + v[5].x; t45.y = v[4].y + v[5].y; t45.z = v[4].z + v[5].z; t45.w = v[4].w + v[5].w;
            t67.x = v[6].x + v[7].x; t67.y = v[6].y + v[7].y; t67.z = v[6].z + v[7].z; t67.w = v[6].w + v[7].w;
            t03.x = t01.x + t23.x; t03.y = t01.y + t23.y; t03.z = t01.z + t23.z; t03.w = t01.w + t23.w;
            t47.x = t45.x + t67.x; t47.y = t45.y + t67.y; t47.z = t45.z + t67.z; t47.w = t45.w + t67.w;
            t.x = t03.x + t47.x; t.y = t03.y + t47.y; t.z = t03.z + t47.z; t.w = t03.w + t47.w;
            acc.x += t.x; acc.y += t.y; acc.z += t.z; acc.w += t.w;
        } else {
            // Slow path (segment boundary inside this group): per-row logic.
            #pragma unroll
            for (int j = 0; j < 8; ++j) {
                int s = braw[(r + j) * stride];
                if (s != cur) {
                    flush_acc(out, cur, lane, acc, max_seg);
                    cur = s;
                    acc = make_float4(0.f, 0.f, 0.f, 0.f);
                }
                acc.x += v[j].x; acc.y += v[j].y; acc.z += v[j].z; acc.w += v[j].w;
            }
        }
    }
    // Tail (< 8 rows)
    for (; r < end; ++r) {
        int s = braw[r * stride];
        float4 vv = __ldcs(&h[(size_t)r * 32 + lane]);
        if (s != cur) {
            flush_acc(out, cur, lane, acc, max_seg);
            cur = s;
            acc = make_float4(0.f, 0.f, 0.f, 0.f);
        }
        acc.x += vv.x; acc.y += vv.y; acc.z += vv.z; acc.w += vv.w;
    }
    // Final flush
    flush_acc(out, cur, lane, acc, max_seg);
}

// ---------------------------------------------------------------------------
// Launch. Inputs: h_t (float32, N*FEAT) and batch (int32 or int64, N).
// Order disambiguated by element count (h_t is FEAT x larger).
// ---------------------------------------------------------------------------
extern "C" void kernel_launch(void* const* d_in, const int* in_sizes, int n_in,
                              void* d_out, int out_size) {
    int hi = 0, bi = 1;
    if (n_in >= 2 && in_sizes[0] < in_sizes[1]) { hi = 1; bi = 0; }

    const float4* h        = (const float4*)d_in[hi];
    const int*    batchRaw = (const int*)d_in[bi];
    float*        out      = (float*)d_out;

    const int n_rows  = in_sizes[bi];
    const int max_seg = out_size / FEAT;

    // 1) fused zero + dtype detect
    int n4 = out_size / 4;
    prologue_kernel<<<(n4 + 255) / 256, 256>>>((float4*)d_out, n4,
                                               batchRaw, n_rows);

    // 2) segment sum — exactly one balanced wave
    seg_sum_kernel<<<TOTAL_CTAS, BLOCK_THREADS>>>(h, batchRaw, out,
                                                  n_rows, max_seg);
}

// round 8
// speedup vs baseline: 1.0038x; 1.0034x over previous
#include <cuda_runtime.h>
#include <cstdint>

// Problem constants (match reference setup_inputs)
#define FEAT        128

// Tuning (R5 shape — marginally best wall time across R5/R6/R7)
#define ROWS_PER_WARP   128
#define WARPS_PER_BLOCK 8
#define BLOCK_THREADS   (WARPS_PER_BLOCK * 32)
#define CTAS_PER_SM     5

// ---------------------------------------------------------------------------
// PDL primitives (PTX, avoids device-runtime API availability concerns)
// ---------------------------------------------------------------------------
__device__ __forceinline__ void pdl_trigger() {
    asm volatile("griddepcontrol.launch_dependents;" ::: "memory");
}
__device__ __forceinline__ void pdl_wait() {
    asm volatile("griddepcontrol.wait;" ::: "memory");
}

// ---------------------------------------------------------------------------
// Kernel 1 (prologue): zero the output, then signal dependents (PDL).
// ---------------------------------------------------------------------------
__global__ void prologue_kernel(float4* __restrict__ out, int n4) {
    int i = blockIdx.x * blockDim.x + threadIdx.x;
    if (i < n4) out[i] = make_float4(0.f, 0.f, 0.f, 0.f);
    pdl_trigger();
}

// ---------------------------------------------------------------------------
// Kernel 2: sorted segment sum.
// One warp owns ROWS_PER_WARP contiguous rows; each lane owns 4 features.
// Sortedness shortcut: per 8-row group load only the LAST id; equality with
// cur implies the whole group is one segment -> branch-free tree accumulate.
// Launched with PDL: runs concurrently with the prologue; pdl_wait() is
// issued lazily before the FIRST output flush, so the 512MB load stream
// overlaps the output zeroing.
// Dtype detect (int32 vs int64 batch) is done inline per warp: odd int32
// words of little-endian int64 (< 2^31) are zero high-halves.
// ---------------------------------------------------------------------------
__device__ __forceinline__ void flush_acc(float* __restrict__ out,
                                          int seg, int lane, const float4& acc,
                                          int max_seg, bool& synced) {
    if (!synced) { pdl_wait(); synced = true; }
    if (seg < 0 || seg >= max_seg) return;  // insurance against bad ids
    float* p = out + (size_t)seg * FEAT + lane * 4;
    atomicAdd(p + 0, acc.x);
    atomicAdd(p + 1, acc.y);
    atomicAdd(p + 2, acc.z);
    atomicAdd(p + 3, acc.w);
}

__global__ __launch_bounds__(BLOCK_THREADS, CTAS_PER_SM)
void seg_sum_kernel(const float4* __restrict__ h,     // [n_rows][32] float4
                    const int* __restrict__ braw,     // batch, stride words
                    float* __restrict__ out,          // [max_seg][FEAT]
                    int n_rows, int max_seg) {
    const int warp_id = blockIdx.x * WARPS_PER_BLOCK + (threadIdx.x >> 5);
    const int lane    = threadIdx.x & 31;

    // Inline dtype detect (warp-wide ballot over odd tail words).
    int didx = n_rows - 1 - 2 * lane;
    if (!(didx & 1)) didx -= 1;                       // force odd index
    int nz = (didx > 0) ? (braw[didx] != 0) : 0;
    const int stride = __any_sync(0xFFFFFFFF, nz) ? 1 : 2;

    int start = warp_id * ROWS_PER_WARP;
    if (start >= n_rows) return;
    int end = min(start + ROWS_PER_WARP, n_rows);

    bool synced = false;
    float4 acc = make_float4(0.f, 0.f, 0.f, 0.f);
    int cur = braw[start * stride];

    int r = start;
    for (; r + 8 <= end; r += 8) {
        // One warp-uniform index load per 8 rows (sorted => s7==cur covers all)
        int s7 = braw[(r + 7) * stride];

        float4 v[8];
        #pragma unroll
        for (int j = 0; j < 8; ++j)
            v[j] = __ldcs(&h[(size_t)(r + j) * 32 + lane]);

        if (s7 == cur) {
            // Fast path: tree-sum the 8 rows, single dependency on acc.
            float4 t01, t23, t45, t67, t03, t47, t;
            t01.x = v[0].x + v[1].x; t01.y = v[0].y + v[1].y; t01.z = v[0].z + v[1].z; t01.w = v[0].w + v[1].w;
            t23.x = v[2].x + v[3].x; t23.y = v[2].y + v[3].y; t23.z = v[2].z + v[3].z; t23.w = v[2].w + v[3].w;
            t45.x = v[4].x + v[5].x; t45.y = v[4].y + v[5].y; t45.z = v[4].z + v[5].z; t45.w = v[4].w + v[5].w;
            t67.x = v[6].x + v[7].x; t67.y = v[6].y + v[7].y; t67.z = v[6].z + v[7].z; t67.w = v[6].w + v[7].w;
            t03.x = t01.x + t23.x; t03.y = t01.y + t23.y; t03.z = t01.z + t23.z; t03.w = t01.w + t23.w;
            t47.x = t45.x + t67.x; t47.y = t45.y + t67.y; t47.z = t45.z + t67.z; t47.w = t45.w + t67.w;
            t.x = t03.x + t47.x; t.y = t03.y + t47.y; t.z = t03.z + t47.z; t.w = t03.w + t47.w;
            acc.x += t.x; acc.y += t.y; acc.z += t.z; acc.w += t.w;
        } else {
            // Slow path (segment boundary inside this group): per-row logic.
            #pragma unroll
            for (int j = 0; j < 8; ++j) {
                int s = braw[(r + j) * stride];
                if (s != cur) {
                    flush_acc(out, cur, lane, acc, max_seg, synced);
                    cur = s;
                    acc = make_float4(0.f, 0.f, 0.f, 0.f);
                }
                acc.x += v[j].x; acc.y += v[j].y; acc.z += v[j].z; acc.w += v[j].w;
            }
        }
    }
    // Tail (< 8 rows)
    for (; r < end; ++r) {
        int s = braw[r * stride];
        float4 vv = __ldcs(&h[(size_t)r * 32 + lane]);
        if (s != cur) {
            flush_acc(out, cur, lane, acc, max_seg, synced);
            cur = s;
            acc = make_float4(0.f, 0.f, 0.f, 0.f);
        }
        acc.x += vv.x; acc.y += vv.y; acc.z += vv.z; acc.w += vv.w;
    }
    // Final flush
    flush_acc(out, cur, lane, acc, max_seg, synced);
}

// ---------------------------------------------------------------------------
// Launch. Inputs: h_t (float32, N*FEAT) and batch (int32 or int64, N).
// Order disambiguated by element count (h_t is FEAT x larger).
// seg_sum is launched with programmatic stream serialization (PDL) so it
// overlaps the prologue's zeroing.
// ---------------------------------------------------------------------------
extern "C" void kernel_launch(void* const* d_in, const int* in_sizes, int n_in,
                              void* d_out, int out_size) {
    int hi = 0, bi = 1;
    if (n_in >= 2 && in_sizes[0] < in_sizes[1]) { hi = 1; bi = 0; }

    const float4* h        = (const float4*)d_in[hi];
    const int*    batchRaw = (const int*)d_in[bi];
    float*        out      = (float*)d_out;

    const int n_rows  = in_sizes[bi];
    const int max_seg = out_size / FEAT;

    // 1) zero output (signals PDL completion when done)
    int n4 = out_size / 4;
    prologue_kernel<<<(n4 + 255) / 256, 256>>>((float4*)d_out, n4);

    // 2) segment sum — PDL launch, overlaps with prologue
    int n_warps  = (n_rows + ROWS_PER_WARP - 1) / ROWS_PER_WARP;
    int n_blocks = (n_warps + WARPS_PER_BLOCK - 1) / WARPS_PER_BLOCK;

    cudaLaunchConfig_t cfg = {};
    cfg.gridDim  = dim3(n_blocks, 1, 1);
    cfg.blockDim = dim3(BLOCK_THREADS, 1, 1);
    cfg.dynamicSmemBytes = 0;
    cfg.stream = 0;  // legacy default stream (same as <<<>>> above)
    cudaLaunchAttribute attrs[1];
    attrs[0].id = cudaLaunchAttributeProgrammaticStreamSerialization;
    attrs[0].val.programmaticStreamSerializationAllowed = 1;
    cfg.attrs = attrs;
    cfg.numAttrs = 1;
    cudaLaunchKernelEx(&cfg, seg_sum_kernel, h, batchRaw, out, n_rows, max_seg);
}